// round 3
// baseline (speedup 1.0000x reference)
#include <cuda_runtime.h>

// ---------------------------------------------------------------------------
// SelfAttention block, fp32 SIMT baseline for sm_100a.
//
// Reference semantics (torch-faithful):
//   tokens n in [0, 8192) are the flat (seq*batch) order of the [2048,4,1024]
//   input; the reshape (NOT transpose) groups attention batches as b = n/2048,
//   t = n%2048. Per-head 64x64 projections share Wq/Wk/Wv across heads.
//   scores scaled by 1/sqrt(1024) = 1/32. Full (non-causal) softmax over 2048.
//   out = q + LayerNorm(concat @ Wl^T) * gamma + beta.
// ---------------------------------------------------------------------------

#define SEQ     2048
#define BATCH   4
#define DM      1024
#define HEADS   16
#define HD      64
#define NTOK    8192       // SEQ*BATCH
#define BHN     64         // BATCH*HEADS

#define QS_PITCH 132       // 128 rows + pad (float4-aligned)
#define KS_PITCH 68        // 64 cols + pad (float4-aligned)

// Scratch (device globals; no runtime allocation allowed).
__device__ float g_Q[BHN * SEQ * HD];     // [bh][t][d]
__device__ float g_K[BHN * SEQ * HD];
__device__ float g_V[BHN * SEQ * HD];
__device__ float g_O[NTOK * DM];          // concat, token-major
__device__ float g_LIN[NTOK * DM];        // pre-LN linear output

// ---------------------------------------------------------------------------
// Kernel 1: QKV projection.
// Input viewed as X[131072, 64] (row r = token n * 16 + head h, contiguous).
// Y[r, e] = sum_d X[r, d] * W[e, d].  Tile: 128 rows x 64 cols, K=64.
// Output scattered to g_{Q,K,V}[(b*16+h)*2048 + t][e].
// ---------------------------------------------------------------------------
__global__ __launch_bounds__(256) void qkv_proj_kernel(
    const float* __restrict__ qin, const float* __restrict__ kin,
    const float* __restrict__ vin,
    const float* __restrict__ Wq, const float* __restrict__ Wk,
    const float* __restrict__ Wv)
{
    extern __shared__ float sm[];
    float* xs = sm;                      // [64][QS_PITCH]  k-major X tile
    float* ws = sm + 64 * QS_PITCH;      // [64][KS_PITCH]  k-major W^T

    const int which = blockIdx.y;
    const float* X = (which == 0) ? qin : (which == 1) ? kin : vin;
    const float* W = (which == 0) ? Wq  : (which == 1) ? Wk  : Wv;
    float* OUT     = (which == 0) ? g_Q : (which == 1) ? g_K : g_V;

    const int tid   = threadIdx.x;
    const int rbase = blockIdx.x * 128;

    // Load W transposed: ws[d][e] = W[e][d]
    const float4* W4 = (const float4*)W;
    #pragma unroll
    for (int i = 0; i < 4; ++i) {
        int lin = tid + 256 * i;          // 0..1023
        int e   = lin >> 4;
        int d4  = lin & 15;
        float4 w = W4[e * 16 + d4];
        ws[(d4 * 4 + 0) * KS_PITCH + e] = w.x;
        ws[(d4 * 4 + 1) * KS_PITCH + e] = w.y;
        ws[(d4 * 4 + 2) * KS_PITCH + e] = w.z;
        ws[(d4 * 4 + 3) * KS_PITCH + e] = w.w;
    }
    // Load X tile transposed: xs[d][r]
    const float4* X4 = (const float4*)X;
    #pragma unroll
    for (int i = 0; i < 8; ++i) {
        int lin = tid + 256 * i;          // 0..2047
        int r   = lin >> 4;               // 0..127
        int d4  = lin & 15;
        float4 x = X4[(rbase + r) * 16 + d4];
        xs[(d4 * 4 + 0) * QS_PITCH + r] = x.x;
        xs[(d4 * 4 + 1) * QS_PITCH + r] = x.y;
        xs[(d4 * 4 + 2) * QS_PITCH + r] = x.z;
        xs[(d4 * 4 + 3) * QS_PITCH + r] = x.w;
    }
    __syncthreads();

    const int ty = tid >> 4, tx = tid & 15;
    const int r0 = ty * 8, c0 = tx * 4;

    float acc[8][4];
    #pragma unroll
    for (int i = 0; i < 8; ++i)
        #pragma unroll
        for (int j = 0; j < 4; ++j) acc[i][j] = 0.f;

    #pragma unroll 8
    for (int d = 0; d < 64; ++d) {
        float a[8], b[4];
        *(float4*)&a[0] = *(const float4*)(xs + d * QS_PITCH + r0);
        *(float4*)&a[4] = *(const float4*)(xs + d * QS_PITCH + r0 + 4);
        *(float4*)&b[0] = *(const float4*)(ws + d * KS_PITCH + c0);
        #pragma unroll
        for (int ii = 0; ii < 8; ++ii)
            #pragma unroll
            for (int jj = 0; jj < 4; ++jj)
                acc[ii][jj] = fmaf(a[ii], b[jj], acc[ii][jj]);
    }

    #pragma unroll
    for (int i = 0; i < 8; ++i) {
        int r = rbase + r0 + i;
        int n = r >> 4, h = r & 15;
        int b = n >> 11, t = n & 2047;
        float4 o = make_float4(acc[i][0], acc[i][1], acc[i][2], acc[i][3]);
        *(float4*)(OUT + ((b * HEADS + h) * SEQ + t) * HD + c0) = o;
    }
}

// ---------------------------------------------------------------------------
// Kernel 2: flash attention, fp32.
// Block = (bh, 128 q-rows). 256 threads, 8x4 register tiles.
// Online softmax with shuffle reductions over the 16-lane tx group.
// ---------------------------------------------------------------------------
__global__ __launch_bounds__(256, 2) void attn_kernel()
{
    extern __shared__ float sm[];
    float* qs = sm;                       // [64][QS_PITCH]  d-major, pre-scaled
    float* ks = qs + 64 * QS_PITCH;       // [64][KS_PITCH]  d-major
    float* vs = ks + 64 * KS_PITCH;       // [64][KS_PITCH]  c-major (natural)
    float* ps = vs + 64 * KS_PITCH;       // [64][QS_PITCH]  c-major P

    const int tid = threadIdx.x;
    const int qb  = blockIdx.x;           // 0..15
    const int bh  = blockIdx.y;           // 0..63

    const float* Qp = g_Q + (bh * SEQ + qb * 128) * HD;
    const float* Kp = g_K + bh * SEQ * HD;
    const float* Vp = g_V + bh * SEQ * HD;

    // Load Q tile transposed, pre-scaled by 1/sqrt(1024) = 1/32.
    const float4* Q4 = (const float4*)Qp;
    #pragma unroll
    for (int i = 0; i < 8; ++i) {
        int lin = tid + 256 * i;
        int r   = lin >> 4, d4 = lin & 15;
        float4 x = Q4[r * 16 + d4];
        qs[(d4 * 4 + 0) * QS_PITCH + r] = x.x * 0.03125f;
        qs[(d4 * 4 + 1) * QS_PITCH + r] = x.y * 0.03125f;
        qs[(d4 * 4 + 2) * QS_PITCH + r] = x.z * 0.03125f;
        qs[(d4 * 4 + 3) * QS_PITCH + r] = x.w * 0.03125f;
    }

    const int ty = tid >> 4, tx = tid & 15;
    const int r0 = ty * 8, c0 = tx * 4;

    float o[8][4];
    float mrow[8], lrow[8];
    #pragma unroll
    for (int i = 0; i < 8; ++i) {
        mrow[i] = -1e30f;
        lrow[i] = 0.f;
        #pragma unroll
        for (int j = 0; j < 4; ++j) o[i][j] = 0.f;
    }

    for (int kt = 0; kt < SEQ / 64; ++kt) {
        __syncthreads();   // previous iter's ks/vs/ps reads done
        const float4* K4 = (const float4*)(Kp + kt * 64 * HD);
        const float4* V4 = (const float4*)(Vp + kt * 64 * HD);
        #pragma unroll
        for (int i = 0; i < 4; ++i) {
            int lin = tid + 256 * i;      // 0..1023
            int c   = lin >> 4, d4 = lin & 15;
            float4 kk = K4[c * 16 + d4];
            ks[(d4 * 4 + 0) * KS_PITCH + c] = kk.x;
            ks[(d4 * 4 + 1) * KS_PITCH + c] = kk.y;
            ks[(d4 * 4 + 2) * KS_PITCH + c] = kk.z;
            ks[(d4 * 4 + 3) * KS_PITCH + c] = kk.w;
            float4 vv = V4[c * 16 + d4];
            *(float4*)(vs + c * KS_PITCH + d4 * 4) = vv;
        }
        __syncthreads();

        // S = (Q/32) @ K^T
        float s[8][4];
        #pragma unroll
        for (int i = 0; i < 8; ++i)
            #pragma unroll
            for (int j = 0; j < 4; ++j) s[i][j] = 0.f;

        #pragma unroll 8
        for (int d = 0; d < 64; ++d) {
            float a[8], b[4];
            *(float4*)&a[0] = *(const float4*)(qs + d * QS_PITCH + r0);
            *(float4*)&a[4] = *(const float4*)(qs + d * QS_PITCH + r0 + 4);
            *(float4*)&b[0] = *(const float4*)(ks + d * KS_PITCH + c0);
            #pragma unroll
            for (int ii = 0; ii < 8; ++ii)
                #pragma unroll
                for (int jj = 0; jj < 4; ++jj)
                    s[ii][jj] = fmaf(a[ii], b[jj], s[ii][jj]);
        }

        // Online softmax update (row stats shared across the 16-lane tx group)
        #pragma unroll
        for (int i = 0; i < 8; ++i) {
            float tm = fmaxf(fmaxf(s[i][0], s[i][1]), fmaxf(s[i][2], s[i][3]));
            tm = fmaxf(tm, __shfl_xor_sync(0xffffffffu, tm, 1));
            tm = fmaxf(tm, __shfl_xor_sync(0xffffffffu, tm, 2));
            tm = fmaxf(tm, __shfl_xor_sync(0xffffffffu, tm, 4));
            tm = fmaxf(tm, __shfl_xor_sync(0xffffffffu, tm, 8));
            float mnew  = fmaxf(mrow[i], tm);
            float alpha = __expf(mrow[i] - mnew);
            mrow[i] = mnew;
            float rs = 0.f;
            #pragma unroll
            for (int jj = 0; jj < 4; ++jj) {
                s[i][jj] = __expf(s[i][jj] - mnew);
                rs += s[i][jj];
            }
            rs += __shfl_xor_sync(0xffffffffu, rs, 1);
            rs += __shfl_xor_sync(0xffffffffu, rs, 2);
            rs += __shfl_xor_sync(0xffffffffu, rs, 4);
            rs += __shfl_xor_sync(0xffffffffu, rs, 8);
            lrow[i] = lrow[i] * alpha + rs;
            #pragma unroll
            for (int jj = 0; jj < 4; ++jj) o[i][jj] *= alpha;
        }

        // Stage P transposed (c-major) for the PV outer product.
        #pragma unroll
        for (int jj = 0; jj < 4; ++jj)
            #pragma unroll
            for (int i = 0; i < 8; ++i)
                ps[(c0 + jj) * QS_PITCH + (r0 + i)] = s[i][jj];
        __syncthreads();

        // O += P @ V
        #pragma unroll 8
        for (int c = 0; c < 64; ++c) {
            float a[8], b[4];
            *(float4*)&a[0] = *(const float4*)(ps + c * QS_PITCH + r0);
            *(float4*)&a[4] = *(const float4*)(ps + c * QS_PITCH + r0 + 4);
            *(float4*)&b[0] = *(const float4*)(vs + c * KS_PITCH + c0);
            #pragma unroll
            for (int ii = 0; ii < 8; ++ii)
                #pragma unroll
                for (int jj = 0; jj < 4; ++jj)
                    o[ii][jj] = fmaf(a[ii], b[jj], o[ii][jj]);
        }
    }

    // Normalize and scatter to token-major concat layout.
    const int b = bh >> 4, h = bh & 15;
    #pragma unroll
    for (int i = 0; i < 8; ++i) {
        float inv = 1.f / lrow[i];
        int t = qb * 128 + r0 + i;
        float4 res = make_float4(o[i][0] * inv, o[i][1] * inv,
                                 o[i][2] * inv, o[i][3] * inv);
        *(float4*)(g_O + (b * SEQ + t) * DM + h * HD + c0) = res;
    }
}

// ---------------------------------------------------------------------------
// Kernel 3: lin = concat @ Wl^T.  M=8192, N=1024, K=1024.
// Tile 128x64, BK=32, 8x4 per-thread.
// ---------------------------------------------------------------------------
__global__ __launch_bounds__(256) void linear_kernel(const float* __restrict__ Wl)
{
    __shared__ float as_[32 * QS_PITCH];   // k-major A tile
    __shared__ float bs [32 * KS_PITCH];   // k-major W^T tile

    const int tid   = threadIdx.x;
    const int rbase = blockIdx.x * 128;
    const int cbase = blockIdx.y * 64;
    const int ty = tid >> 4, tx = tid & 15;
    const int r0 = ty * 8, c0 = tx * 4;

    float acc[8][4];
    #pragma unroll
    for (int i = 0; i < 8; ++i)
        #pragma unroll
        for (int j = 0; j < 4; ++j) acc[i][j] = 0.f;

    const float4* A4 = (const float4*)g_O;
    const float4* B4 = (const float4*)Wl;

    for (int kt = 0; kt < 32; ++kt) {
        __syncthreads();
        #pragma unroll
        for (int i = 0; i < 4; ++i) {
            int lin = tid + 256 * i;       // 0..1023
            int r   = lin >> 3, d4 = lin & 7;
            float4 a = A4[(rbase + r) * 256 + kt * 8 + d4];
            as_[(d4 * 4 + 0) * QS_PITCH + r] = a.x;
            as_[(d4 * 4 + 1) * QS_PITCH + r] = a.y;
            as_[(d4 * 4 + 2) * QS_PITCH + r] = a.z;
            as_[(d4 * 4 + 3) * QS_PITCH + r] = a.w;
        }
        #pragma unroll
        for (int i = 0; i < 2; ++i) {
            int lin = tid + 256 * i;       // 0..511
            int e   = lin >> 3, d4 = lin & 7;
            float4 b = B4[(cbase + e) * 256 + kt * 8 + d4];
            bs[(d4 * 4 + 0) * KS_PITCH + e] = b.x;
            bs[(d4 * 4 + 1) * KS_PITCH + e] = b.y;
            bs[(d4 * 4 + 2) * KS_PITCH + e] = b.z;
            bs[(d4 * 4 + 3) * KS_PITCH + e] = b.w;
        }
        __syncthreads();

        #pragma unroll 8
        for (int d = 0; d < 32; ++d) {
            float a[8], b[4];
            *(float4*)&a[0] = *(const float4*)(as_ + d * QS_PITCH + r0);
            *(float4*)&a[4] = *(const float4*)(as_ + d * QS_PITCH + r0 + 4);
            *(float4*)&b[0] = *(const float4*)(bs + d * KS_PITCH + c0);
            #pragma unroll
            for (int ii = 0; ii < 8; ++ii)
                #pragma unroll
                for (int jj = 0; jj < 4; ++jj)
                    acc[ii][jj] = fmaf(a[ii], b[jj], acc[ii][jj]);
        }
    }

    #pragma unroll
    for (int i = 0; i < 8; ++i) {
        float4 res = make_float4(acc[i][0], acc[i][1], acc[i][2], acc[i][3]);
        *(float4*)(g_LIN + (rbase + r0 + i) * DM + cbase + c0) = res;
    }
}

// ---------------------------------------------------------------------------
// Kernel 4: LayerNorm + residual.  One block per token row.
// ---------------------------------------------------------------------------
__global__ __launch_bounds__(256) void ln_kernel(
    const float* __restrict__ qin, const float* __restrict__ gamma,
    const float* __restrict__ beta, float* __restrict__ out)
{
    const int row = blockIdx.x;
    const int tid = threadIdx.x;

    const float4 x = *(const float4*)(g_LIN + row * DM + tid * 4);
    float s  = x.x + x.y + x.z + x.w;
    float ss = fmaf(x.x, x.x, fmaf(x.y, x.y, fmaf(x.z, x.z, x.w * x.w)));

    #pragma unroll
    for (int m = 16; m >= 1; m >>= 1) {
        s  += __shfl_xor_sync(0xffffffffu, s, m);
        ss += __shfl_xor_sync(0xffffffffu, ss, m);
    }

    __shared__ float rs[8], rss[8];
    __shared__ float sh_mean, sh_rstd;
    const int wid = tid >> 5, lane = tid & 31;
    if (lane == 0) { rs[wid] = s; rss[wid] = ss; }
    __syncthreads();
    if (tid == 0) {
        float S = 0.f, SS = 0.f;
        #pragma unroll
        for (int i = 0; i < 8; ++i) { S += rs[i]; SS += rss[i]; }
        float mean = S * (1.f / DM);
        float var  = SS * (1.f / DM) - mean * mean;
        sh_mean = mean;
        sh_rstd = rsqrtf(var + 1e-5f);
    }
    __syncthreads();

    const float mean = sh_mean, rstd = sh_rstd;
    const float4 g  = *(const float4*)(gamma + tid * 4);
    const float4 bt = *(const float4*)(beta + tid * 4);
    const float4 qv = *(const float4*)(qin + row * DM + tid * 4);
    float4 o;
    o.x = qv.x + (x.x - mean) * rstd * g.x + bt.x;
    o.y = qv.y + (x.y - mean) * rstd * g.y + bt.y;
    o.z = qv.z + (x.z - mean) * rstd * g.z + bt.z;
    o.w = qv.w + (x.w - mean) * rstd * g.w + bt.w;
    *(float4*)(out + row * DM + tid * 4) = o;
}

// ---------------------------------------------------------------------------
// Launch
// ---------------------------------------------------------------------------
extern "C" void kernel_launch(void* const* d_in, const int* in_sizes, int n_in,
                              void* d_out, int out_size)
{
    const float* q     = (const float*)d_in[0];
    const float* k     = (const float*)d_in[1];
    const float* v     = (const float*)d_in[2];
    const float* Wq    = (const float*)d_in[3];
    const float* Wk    = (const float*)d_in[4];
    const float* Wv    = (const float*)d_in[5];
    const float* Wl    = (const float*)d_in[6];
    const float* gamma = (const float*)d_in[7];
    const float* beta  = (const float*)d_in[8];

    const int proj_smem = (64 * QS_PITCH + 64 * KS_PITCH) * (int)sizeof(float); // 51200
    const int attn_smem = (2 * 64 * QS_PITCH + 2 * 64 * KS_PITCH) * (int)sizeof(float); // 102400

    cudaFuncSetAttribute(qkv_proj_kernel,
                         cudaFuncAttributeMaxDynamicSharedMemorySize, proj_smem);
    cudaFuncSetAttribute(attn_kernel,
                         cudaFuncAttributeMaxDynamicSharedMemorySize, attn_smem);

    // 1) QKV projection: 131072 rows / 128 per block, 3 matrices.
    qkv_proj_kernel<<<dim3(1024, 3), 256, proj_smem>>>(q, k, v, Wq, Wk, Wv);

    // 2) Flash attention: 16 q-blocks x 64 (batch*head).
    attn_kernel<<<dim3(16, 64), 256, attn_smem>>>();

    // 3) Output linear: 8192/128 x 1024/64 tiles.
    linear_kernel<<<dim3(64, 16), 256>>>(Wl);

    // 4) LayerNorm + residual.
    ln_kernel<<<NTOK, 256>>>(q, gamma, beta, (float*)d_out);
}